// round 7
// baseline (speedup 1.0000x reference)
#include <cuda_runtime.h>
#include <math.h>

#define FEAT       512
#define FEAT4      128            // FEAT / 4
#define MAX_NSEG   65536
#define VPART_BLKS 32
#define E_PER_BLK  16             // FEAT / VPART_BLKS

__device__ float g_v[FEAT];
__device__ float g_vpart[VPART_BLKS * FEAT];
__device__ float g_c;
__device__ int   g_seg_start[MAX_NSEG + 1];
__device__ int   g_done;          // zero-initialized; reset by reducer each launch

// ---------------------------------------------------------------------------
// Kernel A (fused setup, single launch):
//   blocks [0, VPART_BLKS)            : partial v = W^T q  (+ done-counter)
//   blocks [VPART_BLKS, VPART+off)    : segment start offsets (sorted int32 idx)
//   block  VPART_BLKS + off_blks      : spin on counter, reduce partials -> g_v,
//                                       c = b.q, reset counter for next replay
// ---------------------------------------------------------------------------
__global__ __launch_bounds__(256)
void setup_kernel(const float* __restrict__ W,
                  const float* __restrict__ q,
                  const float* __restrict__ bias,
                  const int* __restrict__ idx,
                  int n, int nseg, int off_blks) {
    const int b = blockIdx.x;
    if (b < VPART_BLKS) {
        #pragma unroll
        for (int half = 0; half < 2; half++) {
            const int d = threadIdx.x + half * 256;
            float acc = 0.0f;
            #pragma unroll
            for (int i = 0; i < E_PER_BLK; i++) {
                int e = b * E_PER_BLK + i;
                acc = fmaf(W[(size_t)e * FEAT + d], __ldg(&q[e]), acc);
            }
            g_vpart[b * FEAT + d] = acc;
        }
        __threadfence();
        __syncthreads();
        if (threadIdx.x == 0) atomicAdd(&g_done, 1);
    } else if (b < VPART_BLKS + off_blks) {
        const int i = (b - VPART_BLKS) * 256 + threadIdx.x;
        if (i >= n) return;
        int cur  = idx[i];
        int prev = (i == 0) ? -1 : idx[i - 1];
        if (cur  > nseg) cur  = nseg;
        if (prev > nseg) prev = nseg;
        for (int s = prev + 1; s <= cur; s++) g_seg_start[s] = i;
        if (i == n - 1) {
            for (int s = cur + 1; s <= nseg; s++) g_seg_start[s] = n;
        }
    } else {
        // reducer block: wait for all vpart blocks of THIS launch
        if (threadIdx.x == 0) {
            while (atomicAdd(&g_done, 0) < VPART_BLKS) { }
        }
        __syncthreads();

        #pragma unroll
        for (int half = 0; half < 2; half++) {
            const int d = threadIdx.x + half * 256;
            float acc = 0.0f;
            #pragma unroll
            for (int p = 0; p < VPART_BLKS; p++) acc += g_vpart[p * FEAT + d];
            g_v[d] = acc;
        }

        // c = bias . q  (256 threads, 2 elements each)
        __shared__ float red[256];
        const int t = threadIdx.x;
        red[t] = bias[t] * q[t] + bias[t + 256] * q[t + 256];
        __syncthreads();
        for (int s = 128; s > 0; s >>= 1) {
            if (t < s) red[t] += red[t + s];
            __syncthreads();
        }
        if (t == 0) {
            g_c = red[0];
            g_done = 0;   // reset for next graph replay (stream-serialized)
        }
    }
}

// ---------------------------------------------------------------------------
// Kernel B: warp-per-segment online-softmax attention pooling.
// Rows processed in PAIRS (MLP=8 LDG.128, streaming). v lives in SHARED
// memory and is consumed chunk-wise (one float4 LDS reused for both rows),
// cutting its register live range 16 -> 4 so 4 blocks/SM fit (64-reg cap).
// No global atomics; features read exactly once.
// ---------------------------------------------------------------------------
#define WARPS_PER_BLK 8

__device__ __forceinline__ float4 ldcs4(const float4* p) {
    return __ldcs(p);
}

__global__ __launch_bounds__(WARPS_PER_BLK * 32, 4)
void warp_pool_kernel(const float* __restrict__ feat,
                      float* __restrict__ out,
                      int nseg) {
    const int wid  = threadIdx.x >> 5;
    const int lane = threadIdx.x & 31;
    const int s    = blockIdx.x * WARPS_PER_BLK + wid;

    __shared__ float4 sv4[FEAT4];
    // cooperative load of v into smem (256 threads, 128 float4s)
    if (threadIdx.x < FEAT4) {
        sv4[threadIdx.x] = ((const float4*)g_v)[threadIdx.x];
    }
    __syncthreads();

    if (s >= nseg) return;

    const int start = g_seg_start[s];
    const int end   = g_seg_start[s + 1];

    float4* orow4 = (float4*)(out + (size_t)s * FEAT);

    if (start >= end) {
        const float4 z = make_float4(0.f, 0.f, 0.f, 0.f);
        __stcs(&orow4[lane], z);
        __stcs(&orow4[32 + lane], z);
        __stcs(&orow4[64 + lane], z);
        __stcs(&orow4[96 + lane], z);
        return;
    }

    const float c = g_c;

    float m   = -INFINITY;
    float den = 0.0f;
    float4 a0 = make_float4(0.f, 0.f, 0.f, 0.f);
    float4 a1 = a0, a2 = a0, a3 = a0;

    const float4* feat4 = (const float4*)feat;

    int r = start;
    for (; r + 1 < end; r += 2) {
        // ---- both rows' loads issue before any dependent compute ----
        const float4* rowA = feat4 + (size_t)r * FEAT4;
        const float4* rowB = rowA + FEAT4;
        float4 f0 = ldcs4(&rowA[lane]);
        float4 f1 = ldcs4(&rowA[32 + lane]);
        float4 f2 = ldcs4(&rowA[64 + lane]);
        float4 f3 = ldcs4(&rowA[96 + lane]);
        float4 g0 = ldcs4(&rowB[lane]);
        float4 g1 = ldcs4(&rowB[32 + lane]);
        float4 g2 = ldcs4(&rowB[64 + lane]);
        float4 g3 = ldcs4(&rowB[96 + lane]);

        // ---- two independent dot products, v consumed chunk-wise ----
        float p0, p1;
        {
            float4 vv = sv4[lane];
            p0 = f0.x * vv.x;          p1 = g0.x * vv.x;
            p0 = fmaf(f0.y, vv.y, p0); p1 = fmaf(g0.y, vv.y, p1);
            p0 = fmaf(f0.z, vv.z, p0); p1 = fmaf(g0.z, vv.z, p1);
            p0 = fmaf(f0.w, vv.w, p0); p1 = fmaf(g0.w, vv.w, p1);
            vv = sv4[32 + lane];
            p0 = fmaf(f1.x, vv.x, p0); p1 = fmaf(g1.x, vv.x, p1);
            p0 = fmaf(f1.y, vv.y, p0); p1 = fmaf(g1.y, vv.y, p1);
            p0 = fmaf(f1.z, vv.z, p0); p1 = fmaf(g1.z, vv.z, p1);
            p0 = fmaf(f1.w, vv.w, p0); p1 = fmaf(g1.w, vv.w, p1);
            vv = sv4[64 + lane];
            p0 = fmaf(f2.x, vv.x, p0); p1 = fmaf(g2.x, vv.x, p1);
            p0 = fmaf(f2.y, vv.y, p0); p1 = fmaf(g2.y, vv.y, p1);
            p0 = fmaf(f2.z, vv.z, p0); p1 = fmaf(g2.z, vv.z, p1);
            p0 = fmaf(f2.w, vv.w, p0); p1 = fmaf(g2.w, vv.w, p1);
            vv = sv4[96 + lane];
            p0 = fmaf(f3.x, vv.x, p0); p1 = fmaf(g3.x, vv.x, p1);
            p0 = fmaf(f3.y, vv.y, p0); p1 = fmaf(g3.y, vv.y, p1);
            p0 = fmaf(f3.z, vv.z, p0); p1 = fmaf(g3.z, vv.z, p1);
            p0 = fmaf(f3.w, vv.w, p0); p1 = fmaf(g3.w, vv.w, p1);
        }

        // ---- interleaved warp allreduces (independent shfl chains) ----
        #pragma unroll
        for (int o = 16; o > 0; o >>= 1) {
            p0 += __shfl_xor_sync(0xffffffffu, p0, o);
            p1 += __shfl_xor_sync(0xffffffffu, p1, o);
        }

        // ---- joint online softmax update for both rows ----
        const float sc0 = p0 + c;
        const float sc1 = p1 + c;
        const float mn  = fmaxf(m, fmaxf(sc0, sc1));
        const float scale = __expf(m - mn);     // m=-inf initially -> 0
        const float w0  = __expf(sc0 - mn);
        const float w1  = __expf(sc1 - mn);
        den = fmaf(den, scale, w0 + w1);

        a0.x = fmaf(w1, g0.x, fmaf(w0, f0.x, a0.x * scale));
        a0.y = fmaf(w1, g0.y, fmaf(w0, f0.y, a0.y * scale));
        a0.z = fmaf(w1, g0.z, fmaf(w0, f0.z, a0.z * scale));
        a0.w = fmaf(w1, g0.w, fmaf(w0, f0.w, a0.w * scale));
        a1.x = fmaf(w1, g1.x, fmaf(w0, f1.x, a1.x * scale));
        a1.y = fmaf(w1, g1.y, fmaf(w0, f1.y, a1.y * scale));
        a1.z = fmaf(w1, g1.z, fmaf(w0, f1.z, a1.z * scale));
        a1.w = fmaf(w1, g1.w, fmaf(w0, f1.w, a1.w * scale));
        a2.x = fmaf(w1, g2.x, fmaf(w0, f2.x, a2.x * scale));
        a2.y = fmaf(w1, g2.y, fmaf(w0, f2.y, a2.y * scale));
        a2.z = fmaf(w1, g2.z, fmaf(w0, f2.z, a2.z * scale));
        a2.w = fmaf(w1, g2.w, fmaf(w0, f2.w, a2.w * scale));
        a3.x = fmaf(w1, g3.x, fmaf(w0, f3.x, a3.x * scale));
        a3.y = fmaf(w1, g3.y, fmaf(w0, f3.y, a3.y * scale));
        a3.z = fmaf(w1, g3.z, fmaf(w0, f3.z, a3.z * scale));
        a3.w = fmaf(w1, g3.w, fmaf(w0, f3.w, a3.w * scale));

        m = mn;
    }

    // ---- tail: at most one leftover row ----
    if (r < end) {
        const float4* row = feat4 + (size_t)r * FEAT4;
        float4 f0 = ldcs4(&row[lane]);
        float4 f1 = ldcs4(&row[32 + lane]);
        float4 f2 = ldcs4(&row[64 + lane]);
        float4 f3 = ldcs4(&row[96 + lane]);

        float p;
        {
            float4 vv = sv4[lane];
            p = f0.x * vv.x;
            p = fmaf(f0.y, vv.y, p); p = fmaf(f0.z, vv.z, p); p = fmaf(f0.w, vv.w, p);
            vv = sv4[32 + lane];
            p = fmaf(f1.x, vv.x, p); p = fmaf(f1.y, vv.y, p);
            p = fmaf(f1.z, vv.z, p); p = fmaf(f1.w, vv.w, p);
            vv = sv4[64 + lane];
            p = fmaf(f2.x, vv.x, p); p = fmaf(f2.y, vv.y, p);
            p = fmaf(f2.z, vv.z, p); p = fmaf(f2.w, vv.w, p);
            vv = sv4[96 + lane];
            p = fmaf(f3.x, vv.x, p); p = fmaf(f3.y, vv.y, p);
            p = fmaf(f3.z, vv.z, p); p = fmaf(f3.w, vv.w, p);
        }

        #pragma unroll
        for (int o = 16; o > 0; o >>= 1)
            p += __shfl_xor_sync(0xffffffffu, p, o);

        const float sc    = p + c;
        const float mn    = fmaxf(m, sc);
        const float scale = __expf(m - mn);
        const float wr    = __expf(sc - mn);
        den = fmaf(den, scale, wr);

        a0.x = fmaf(wr, f0.x, a0.x * scale); a0.y = fmaf(wr, f0.y, a0.y * scale);
        a0.z = fmaf(wr, f0.z, a0.z * scale); a0.w = fmaf(wr, f0.w, a0.w * scale);
        a1.x = fmaf(wr, f1.x, a1.x * scale); a1.y = fmaf(wr, f1.y, a1.y * scale);
        a1.z = fmaf(wr, f1.z, a1.z * scale); a1.w = fmaf(wr, f1.w, a1.w * scale);
        a2.x = fmaf(wr, f2.x, a2.x * scale); a2.y = fmaf(wr, f2.y, a2.y * scale);
        a2.z = fmaf(wr, f2.z, a2.z * scale); a2.w = fmaf(wr, f2.w, a2.w * scale);
        a3.x = fmaf(wr, f3.x, a3.x * scale); a3.y = fmaf(wr, f3.y, a3.y * scale);
        a3.z = fmaf(wr, f3.z, a3.z * scale); a3.w = fmaf(wr, f3.w, a3.w * scale);
    }

    const float inv = 1.0f / den;
    a0.x *= inv; a0.y *= inv; a0.z *= inv; a0.w *= inv;
    a1.x *= inv; a1.y *= inv; a1.z *= inv; a1.w *= inv;
    a2.x *= inv; a2.y *= inv; a2.z *= inv; a2.w *= inv;
    a3.x *= inv; a3.y *= inv; a3.z *= inv; a3.w *= inv;
    __stcs(&orow4[lane],      a0);
    __stcs(&orow4[32 + lane], a1);
    __stcs(&orow4[64 + lane], a2);
    __stcs(&orow4[96 + lane], a3);
}

// ---------------------------------------------------------------------------
// Launch
// Inputs: features [N,512] f32, residue_index [N] int32,
//         proj_w [512,512] f32, proj_b [512] f32, query [512] f32
// Output: [NSEG, 512] f32
// ---------------------------------------------------------------------------
extern "C" void kernel_launch(void* const* d_in, const int* in_sizes, int n_in,
                              void* d_out, int out_size) {
    const float* features = (const float*)d_in[0];
    const int*   ridx     = (const int*)d_in[1];
    const float* proj_w   = (const float*)d_in[2];
    const float* proj_b   = (const float*)d_in[3];
    const float* query    = (const float*)d_in[4];
    float*       out      = (float*)d_out;

    const int n_atoms = in_sizes[1];
    const int nseg    = out_size / FEAT;

    const int off_blks = (n_atoms + 255) / 256;
    setup_kernel<<<VPART_BLKS + off_blks + 1, 256>>>(proj_w, query, proj_b,
                                                     ridx, n_atoms, nseg, off_blks);

    const int nblk = (nseg + WARPS_PER_BLK - 1) / WARPS_PER_BLK;
    warp_pool_kernel<<<nblk, WARPS_PER_BLK * 32>>>(features, out, nseg);
}